// round 1
// baseline (speedup 1.0000x reference)
#include <cuda_runtime.h>

#define PNUM 8
#define DDIM 512
#define ADIM 64
#define XDIM (DDIM + ADIM)   // 576
#define HDIM 1024
#define BMAX 16384
#define MAXROWS (BMAX + PNUM * 128)
#define MAXT ((BMAX / 128) + PNUM)

// ---------------- device scratch (no allocations allowed) ----------------
__device__ int   d_counts[PNUM];
__device__ int   d_cursor[PNUM];
__device__ int   d_pstart[PNUM];
__device__ int   d_numtiles;
__device__ int   d_is64;
__device__ int   d_tile_policy[MAXT];
__device__ int   d_tile_vrows[MAXT];
__device__ int   d_tile_row0[MAXT];
__device__ int   d_row_id[MAXROWS];
__device__ float d_hbuf[(size_t)MAXROWS * HDIM];   // ~71 MB fp32 scratch for h

// ---------------- helpers ----------------
__device__ __forceinline__ int get_pidx(const void* pi, int b) {
    if (d_is64) return (int)(((const long long*)pi)[b]);
    return ((const int*)pi)[b];
}

// ---------------- setup kernels ----------------
__global__ void k_reset() {
    int t = threadIdx.x;
    if (t < PNUM) { d_counts[t] = 0; d_cursor[t] = 0; }
}

// Detect int32 vs int64 policy_indices from the byte pattern.
// int64 little-endian values in [0,8) => every odd int32 word is 0.
__global__ void k_detect(const int* pi32, int B) {
    if (threadIdx.x == 0 && blockIdx.x == 0) {
        int n = B < 64 ? B : 64;
        int is64 = 1;
        for (int i = 0; i < n; i++) {
            int lo = pi32[2 * i];
            int hi = pi32[2 * i + 1];
            if (hi != 0 || lo < 0 || lo >= PNUM) { is64 = 0; break; }
        }
        d_is64 = is64;
    }
}

__global__ void k_count(const void* __restrict__ pi, int B) {
    int b = blockIdx.x * blockDim.x + threadIdx.x;
    if (b < B) atomicAdd(&d_counts[get_pidx(pi, b)], 1);
}

__global__ void k_plan() {
    if (threadIdx.x != 0 || blockIdx.x != 0) return;
    int off = 0, t = 0;
    for (int p = 0; p < PNUM; p++) {
        d_pstart[p] = off;
        int c = d_counts[p];
        int nt = (c + 127) >> 7;
        for (int i = 0; i < nt; i++) {
            d_tile_policy[t] = p;
            d_tile_row0[t]   = off + i * 128;
            int rem = c - i * 128;
            d_tile_vrows[t]  = rem < 128 ? rem : 128;
            t++;
        }
        off += nt * 128;
    }
    d_numtiles = t;
}

__global__ void k_scatter(const void* __restrict__ pi, int B) {
    int b = blockIdx.x * blockDim.x + threadIdx.x;
    if (b < B) {
        int p = get_pidx(pi, b);
        int pos = d_pstart[p] + atomicAdd(&d_cursor[p], 1);
        d_row_id[pos] = b;
    }
}

// ---------------- GEMM 1: h = relu(x @ W1[p] + b1[p]) ----------------
// x gathered via d_row_id; x = [latents(512) | actions(64)].
// 128x128 tile, BK=8, 256 threads, 8x8 micro-tile per thread.
__global__ __launch_bounds__(256) void k_gemm1(
    const float* __restrict__ latents, const float* __restrict__ actions,
    const float* __restrict__ W1, const float* __restrict__ b1)
{
    const int t = blockIdx.y;
    if (t >= d_numtiles) return;
    const int p     = d_tile_policy[t];
    const int row0  = d_tile_row0[t];
    const int vrows = d_tile_vrows[t];
    const int n0    = blockIdx.x * 128;

    __shared__ float As[8][128];
    __shared__ float Bs[8][128];

    const int tid   = threadIdx.x;
    const int a_row = tid >> 1;
    const int a_k   = (tid & 1) * 4;
    const int b_k   = tid >> 5;
    const int b_col = (tid & 31) * 4;
    const int ty    = tid >> 4;
    const int tx    = tid & 15;

    const bool avalid = a_row < vrows;
    int rb = 0;
    if (avalid) rb = d_row_id[row0 + a_row];
    const float* __restrict__ lat = latents + (size_t)rb * DDIM;
    const float* __restrict__ act = actions + (size_t)rb * ADIM;
    const float* __restrict__ Wb  = W1 + (size_t)p * XDIM * HDIM + n0;

    float acc[8][8];
#pragma unroll
    for (int i = 0; i < 8; i++)
#pragma unroll
        for (int j = 0; j < 8; j++) acc[i][j] = 0.f;

    float4 aR = make_float4(0.f, 0.f, 0.f, 0.f), bR;
    {
        int k0 = a_k;
        if (avalid)
            aR = (k0 < DDIM) ? *(const float4*)(lat + k0)
                             : *(const float4*)(act + (k0 - DDIM));
        bR = *(const float4*)(Wb + (size_t)b_k * HDIM + b_col);
    }
    const int KT = XDIM / 8;  // 72
    for (int kt = 0; kt < KT; kt++) {
        As[a_k + 0][a_row] = aR.x;
        As[a_k + 1][a_row] = aR.y;
        As[a_k + 2][a_row] = aR.z;
        As[a_k + 3][a_row] = aR.w;
        *(float4*)(&Bs[b_k][b_col]) = bR;
        __syncthreads();
        if (kt + 1 < KT) {
            int k0 = (kt + 1) * 8 + a_k;
            if (avalid)
                aR = (k0 < DDIM) ? *(const float4*)(lat + k0)
                                 : *(const float4*)(act + (k0 - DDIM));
            bR = *(const float4*)(Wb + (size_t)((kt + 1) * 8 + b_k) * HDIM + b_col);
        }
#pragma unroll
        for (int k = 0; k < 8; k++) {
            float af[8], bf[8];
            *(float4*)(af)     = *(const float4*)(&As[k][ty * 8]);
            *(float4*)(af + 4) = *(const float4*)(&As[k][ty * 8 + 4]);
            *(float4*)(bf)     = *(const float4*)(&Bs[k][tx * 8]);
            *(float4*)(bf + 4) = *(const float4*)(&Bs[k][tx * 8 + 4]);
#pragma unroll
            for (int i = 0; i < 8; i++)
#pragma unroll
                for (int j = 0; j < 8; j++)
                    acc[i][j] = fmaf(af[i], bf[j], acc[i][j]);
        }
        __syncthreads();
    }

    // epilogue: +b1, relu, store to padded h scratch (all 128 rows)
    float bb[8];
#pragma unroll
    for (int j = 0; j < 8; j++) bb[j] = b1[p * HDIM + n0 + tx * 8 + j];
#pragma unroll
    for (int i = 0; i < 8; i++) {
        float o[8];
#pragma unroll
        for (int j = 0; j < 8; j++) o[j] = fmaxf(acc[i][j] + bb[j], 0.f);
        float* dst = d_hbuf + (size_t)(row0 + ty * 8 + i) * HDIM + n0 + tx * 8;
        *(float4*)(dst)     = *(float4*)(o);
        *(float4*)(dst + 4) = *(float4*)(o + 4);
    }
}

// ---------------- GEMM 2: y = h @ W2[p] + b2[p], scatter to out ----------------
__global__ __launch_bounds__(256) void k_gemm2(
    const float* __restrict__ W2, const float* __restrict__ b2,
    float* __restrict__ out)
{
    const int t = blockIdx.y;
    if (t >= d_numtiles) return;
    const int p     = d_tile_policy[t];
    const int row0  = d_tile_row0[t];
    const int vrows = d_tile_vrows[t];
    const int n0    = blockIdx.x * 128;

    __shared__ float As[8][128];
    __shared__ float Bs[8][128];

    const int tid   = threadIdx.x;
    const int a_row = tid >> 1;
    const int a_k   = (tid & 1) * 4;
    const int b_k   = tid >> 5;
    const int b_col = (tid & 31) * 4;
    const int ty    = tid >> 4;
    const int tx    = tid & 15;

    const float* __restrict__ Ab = d_hbuf + (size_t)(row0 + a_row) * HDIM;
    const float* __restrict__ Wb = W2 + (size_t)p * HDIM * DDIM + n0;

    float acc[8][8];
#pragma unroll
    for (int i = 0; i < 8; i++)
#pragma unroll
        for (int j = 0; j < 8; j++) acc[i][j] = 0.f;

    float4 aR, bR;
    aR = *(const float4*)(Ab + a_k);
    bR = *(const float4*)(Wb + (size_t)b_k * DDIM + b_col);

    const int KT = HDIM / 8;  // 128
    for (int kt = 0; kt < KT; kt++) {
        As[a_k + 0][a_row] = aR.x;
        As[a_k + 1][a_row] = aR.y;
        As[a_k + 2][a_row] = aR.z;
        As[a_k + 3][a_row] = aR.w;
        *(float4*)(&Bs[b_k][b_col]) = bR;
        __syncthreads();
        if (kt + 1 < KT) {
            int k0 = (kt + 1) * 8;
            aR = *(const float4*)(Ab + k0 + a_k);
            bR = *(const float4*)(Wb + (size_t)(k0 + b_k) * DDIM + b_col);
        }
#pragma unroll
        for (int k = 0; k < 8; k++) {
            float af[8], bf[8];
            *(float4*)(af)     = *(const float4*)(&As[k][ty * 8]);
            *(float4*)(af + 4) = *(const float4*)(&As[k][ty * 8 + 4]);
            *(float4*)(bf)     = *(const float4*)(&Bs[k][tx * 8]);
            *(float4*)(bf + 4) = *(const float4*)(&Bs[k][tx * 8 + 4]);
#pragma unroll
            for (int i = 0; i < 8; i++)
#pragma unroll
                for (int j = 0; j < 8; j++)
                    acc[i][j] = fmaf(af[i], bf[j], acc[i][j]);
        }
        __syncthreads();
    }

    float bb[8];
#pragma unroll
    for (int j = 0; j < 8; j++) bb[j] = b2[p * DDIM + n0 + tx * 8 + j];
#pragma unroll
    for (int i = 0; i < 8; i++) {
        int m = ty * 8 + i;
        if (m < vrows) {
            int b = d_row_id[row0 + m];
            float o[8];
#pragma unroll
            for (int j = 0; j < 8; j++) o[j] = acc[i][j] + bb[j];
            float* dst = out + (size_t)b * DDIM + n0 + tx * 8;
            *(float4*)(dst)     = *(float4*)(o);
            *(float4*)(dst + 4) = *(float4*)(o + 4);
        }
    }
}

// ---------------- launch ----------------
extern "C" void kernel_launch(void* const* d_in, const int* in_sizes, int n_in,
                              void* d_out, int out_size)
{
    const float* latents = (const float*)d_in[0];
    const float* actions = (const float*)d_in[1];
    const void*  pidx    = d_in[2];
    const float* W1      = (const float*)d_in[3];
    const float* b1      = (const float*)d_in[4];
    const float* W2      = (const float*)d_in[5];
    const float* b2      = (const float*)d_in[6];
    float*       out     = (float*)d_out;

    int B = in_sizes[0] / DDIM;   // 16384

    k_reset<<<1, 32>>>();
    k_detect<<<1, 32>>>((const int*)pidx, B);
    k_count<<<(B + 255) / 256, 256>>>(pidx, B);
    k_plan<<<1, 1>>>();
    k_scatter<<<(B + 255) / 256, 256>>>(pidx, B);

    int maxt = (B + 127) / 128 + PNUM;
    dim3 g1(HDIM / 128, maxt);
    dim3 g2(DDIM / 128, maxt);
    k_gemm1<<<g1, 256>>>(latents, actions, W1, b1);
    k_gemm2<<<g2, 256>>>(W2, b2, out);
}

// round 3
// speedup vs baseline: 3.2675x; 3.2675x over previous
#include <cuda_runtime.h>
#include <cstdint>

#define PNUM 8
#define DDIM 512
#define ADIM 64
#define XDIM 576
#define HDIM 1024
#define MAXT 136
#define MAXROWS (MAXT * 128)

// ---------------- device scratch ----------------
__device__ int d_counts[PNUM];
__device__ int d_cursor[PNUM];
__device__ int d_pstart[PNUM];
__device__ int d_numtiles;
__device__ int d_is64;
__device__ int d_tile_policy[MAXT];
__device__ int d_tile_vrows[MAXT];
__device__ int d_tile_row0[MAXT];
__device__ int d_row_id[MAXROWS];
__device__ __align__(128) float d_hbuf[(size_t)MAXROWS * HDIM];   // 71 MB

// ---------------- helpers ----------------
__device__ __forceinline__ void cpasync16(uint32_t dst, const void* src, int srcsz) {
    asm volatile("cp.async.cg.shared.global [%0], [%1], 16, %2;\n"
                 :: "r"(dst), "l"(src), "r"(srcsz) : "memory");
}
#define CP_COMMIT() asm volatile("cp.async.commit_group;\n" ::: "memory")
#define CP_WAIT(n)  asm volatile("cp.async.wait_group " #n ";\n" ::: "memory")

__device__ __forceinline__ uint32_t smem_u32(const void* p) {
    uint32_t a;
    asm("{ .reg .u64 t; cvta.to.shared.u64 t, %1; cvt.u32.u64 %0, t; }" : "=r"(a) : "l"(p));
    return a;
}
__device__ __forceinline__ uint32_t tf32u(float x) {
    uint32_t u;
    asm("cvt.rn.tf32.f32 %0, %1;" : "=r"(u) : "f"(x));
    return u;
}
__device__ __forceinline__ void mma_tf32(float* c, const uint32_t* a, const uint32_t* b) {
    asm volatile(
        "mma.sync.aligned.m16n8k8.row.col.f32.tf32.tf32.f32 "
        "{%0,%1,%2,%3}, {%4,%5,%6,%7}, {%8,%9}, {%0,%1,%2,%3};"
        : "+f"(c[0]), "+f"(c[1]), "+f"(c[2]), "+f"(c[3])
        : "r"(a[0]), "r"(a[1]), "r"(a[2]), "r"(a[3]), "r"(b[0]), "r"(b[1]));
}

__device__ __forceinline__ int get_pidx(const void* pi, int b) {
    if (d_is64) return (int)(((const long long*)pi)[b]);
    return ((const int*)pi)[b];
}

// ---------------- setup kernels ----------------
__global__ void k_init(const int* pi32, int B) {
    int t = threadIdx.x;
    if (t < PNUM) { d_counts[t] = 0; d_cursor[t] = 0; }
    if (t == 0) {
        int n = B < 64 ? B : 64;
        int is64 = 1;
        for (int i = 0; i < n; i++) {
            int lo = pi32[2 * i], hi = pi32[2 * i + 1];
            if (hi != 0 || lo < 0 || lo >= PNUM) { is64 = 0; break; }
        }
        d_is64 = is64;
    }
}
__global__ void k_count(const void* __restrict__ pi, int B) {
    int b = blockIdx.x * blockDim.x + threadIdx.x;
    if (b < B) atomicAdd(&d_counts[get_pidx(pi, b)], 1);
}
__global__ void k_plan() {
    if (threadIdx.x != 0 || blockIdx.x != 0) return;
    int off = 0, t = 0;
    for (int p = 0; p < PNUM; p++) {
        d_pstart[p] = off;
        int c = d_counts[p];
        int nt = (c + 127) >> 7;
        for (int i = 0; i < nt; i++) {
            d_tile_policy[t] = p;
            d_tile_row0[t] = off + i * 128;
            int rem = c - i * 128;
            d_tile_vrows[t] = rem < 128 ? rem : 128;
            t++;
        }
        off += nt * 128;
    }
    d_numtiles = t;
}
__global__ void k_scatter(const void* __restrict__ pi, int B) {
    int b = blockIdx.x * blockDim.x + threadIdx.x;
    if (b < B) {
        int p = get_pidx(pi, b);
        int pos = d_pstart[p] + atomicAdd(&d_cursor[p], 1);
        d_row_id[pos] = b;
    }
}

// ---------------- SMEM layout ----------------
// A tile: 128 rows x 32 k, row stride 36 floats (conflict-free frag loads: bank=4g+t)
// B tile: 32 k-rows x 128 n, row stride 136 floats (bank=8t+g)
#define ASTRIDE 36
#define BSTRIDE 136
#define ABYTES  (128 * ASTRIDE * 4)          // 18432
#define BBYTES  (32 * BSTRIDE * 4)           // 17408
#define STAGE   (ABYTES + BBYTES)            // 35840
#define SMEM_TOTAL (2 * STAGE)               // 71680

// ---------------- fused tf32 mma.sync GEMM body ----------------
// LAYER==1: A = gather(x=[latents|actions]) via d_row_id, K=576,  N-tiles of 128 over HDIM,
//           epilogue relu(+b1) -> d_hbuf (all 128 rows incl. pad).
// LAYER==2: A = d_hbuf rows,                K=1024, N-tiles of 128 over DDIM,
//           epilogue (+b2) -> scatter to out via d_row_id.
template <int LAYER>
__global__ __launch_bounds__(256, 2) void k_mma(
    const float* __restrict__ latents, const float* __restrict__ actions,
    const float* __restrict__ W, const float* __restrict__ bias,
    float* __restrict__ out)
{
    const int t = blockIdx.y;
    if (t >= d_numtiles) return;
    const int p     = d_tile_policy[t];
    const int row0  = d_tile_row0[t];
    const int vrows = d_tile_vrows[t];
    const int n0    = blockIdx.x * 128;

    constexpr int KDIM = (LAYER == 1) ? XDIM : HDIM;
    constexpr int NDIM = (LAYER == 1) ? HDIM : DDIM;
    constexpr int KT   = KDIM / 32;

    extern __shared__ char smem[];
    __shared__ int rid_s[128];
    const uint32_t sb = smem_u32(smem);

    const int tid = threadIdx.x;
    if (tid < 128) rid_s[tid] = (tid < vrows) ? d_row_id[row0 + tid] : -1;
    __syncthreads();

    const float* __restrict__ Wp = W + (size_t)p * KDIM * NDIM + n0;

    // ---- async tile loader ----
    auto load_chunk = [&](int chunk, int slot) {
        const int kc = chunk * 32;
        const uint32_t abase = sb + slot * STAGE;
        const uint32_t bbase = abase + ABYTES;
        // A: 128 rows x 8 segs of 16B
#pragma unroll
        for (int tt = 0; tt < 4; tt++) {
            int j = tid + tt * 256;
            int row = j >> 3, seg = j & 7;
            uint32_t dst = abase + row * (ASTRIDE * 4) + seg * 16;
            if (LAYER == 1) {
                int b = rid_s[row];
                int k = kc + seg * 4;
                const float* src; int sz;
                if (b < 0) { src = latents; sz = 0; }
                else if (k < DDIM) { src = latents + (size_t)b * DDIM + k; sz = 16; }
                else { src = actions + (size_t)b * ADIM + (k - DDIM); sz = 16; }
                cpasync16(dst, src, sz);
            } else {
                cpasync16(dst, d_hbuf + (size_t)(row0 + row) * HDIM + kc + seg * 4, 16);
            }
        }
        // B: 32 k-rows x 32 segs of 16B (natural K-major weight layout)
#pragma unroll
        for (int tt = 0; tt < 4; tt++) {
            int j = tid + tt * 256;
            int kr = j >> 5, seg = j & 31;
            cpasync16(bbase + kr * (BSTRIDE * 4) + seg * 16,
                      Wp + (size_t)(kc + kr) * NDIM + seg * 4, 16);
        }
        CP_COMMIT();
    };

    // ---- fragment indices ----
    const int lane = tid & 31, warp = tid >> 5;
    const int wm = warp >> 2, wn = warp & 3;   // 2 x 4 warp grid
    const int g = lane >> 2, tq = lane & 3;

    float acc[4][4][4];
#pragma unroll
    for (int i = 0; i < 4; i++)
#pragma unroll
        for (int j = 0; j < 4; j++)
#pragma unroll
            for (int q = 0; q < 4; q++) acc[i][j][q] = 0.f;

    load_chunk(0, 0);

    for (int c = 0; c < KT; c++) {
        if (c + 1 < KT) { load_chunk(c + 1, (c + 1) & 1); CP_WAIT(1); }
        else            { CP_WAIT(0); }
        __syncthreads();

        const float* As = (const float*)(smem + (c & 1) * STAGE);
        const float* Bs = (const float*)(smem + (c & 1) * STAGE + ABYTES);

#pragma unroll
        for (int ks = 0; ks < 4; ks++) {
            const int k0 = ks * 8;
            uint32_t a[4][4], b[4][2];
#pragma unroll
            for (int i = 0; i < 4; i++) {
                const float* ap = As + (wm * 64 + i * 16 + g) * ASTRIDE + k0 + tq;
                a[i][0] = tf32u(ap[0]);
                a[i][1] = tf32u(ap[8 * ASTRIDE]);
                a[i][2] = tf32u(ap[4]);
                a[i][3] = tf32u(ap[8 * ASTRIDE + 4]);
            }
#pragma unroll
            for (int j = 0; j < 4; j++) {
                const float* bp = Bs + (k0 + tq) * BSTRIDE + wn * 32 + j * 8 + g;
                b[j][0] = tf32u(bp[0]);
                b[j][1] = tf32u(bp[4 * BSTRIDE]);
            }
#pragma unroll
            for (int i = 0; i < 4; i++)
#pragma unroll
                for (int j = 0; j < 4; j++)
                    mma_tf32(acc[i][j], a[i], b[j]);
        }
        __syncthreads();
    }

    // ---- epilogue ----
    const float* bp = bias + p * NDIM + n0;
    if (LAYER == 1) {
        float* hb = d_hbuf + (size_t)row0 * HDIM + n0;
#pragma unroll
        for (int j = 0; j < 4; j++) {
            int col = wn * 32 + j * 8 + 2 * tq;
            float bx = bp[col], by = bp[col + 1];
#pragma unroll
            for (int i = 0; i < 4; i++) {
                int r0 = wm * 64 + i * 16 + g;
                float2 v0 = make_float2(fmaxf(acc[i][j][0] + bx, 0.f),
                                        fmaxf(acc[i][j][1] + by, 0.f));
                float2 v1 = make_float2(fmaxf(acc[i][j][2] + bx, 0.f),
                                        fmaxf(acc[i][j][3] + by, 0.f));
                *(float2*)(hb + (size_t)r0 * HDIM + col)       = v0;
                *(float2*)(hb + (size_t)(r0 + 8) * HDIM + col) = v1;
            }
        }
    } else {
#pragma unroll
        for (int i = 0; i < 4; i++) {
            int r0 = wm * 64 + i * 16 + g;
            int b0 = rid_s[r0], b1i = rid_s[r0 + 8];
#pragma unroll
            for (int j = 0; j < 4; j++) {
                int col = wn * 32 + j * 8 + 2 * tq;
                float bx = bp[col], by = bp[col + 1];
                if (b0 >= 0) {
                    float2 v = make_float2(acc[i][j][0] + bx, acc[i][j][1] + by);
                    *(float2*)(out + (size_t)b0 * DDIM + n0 + col) = v;
                }
                if (b1i >= 0) {
                    float2 v = make_float2(acc[i][j][2] + bx, acc[i][j][3] + by);
                    *(float2*)(out + (size_t)b1i * DDIM + n0 + col) = v;
                }
            }
        }
    }
}

// ---------------- launch ----------------
extern "C" void kernel_launch(void* const* d_in, const int* in_sizes, int n_in,
                              void* d_out, int out_size)
{
    const float* latents = (const float*)d_in[0];
    const float* actions = (const float*)d_in[1];
    const void*  pidx    = d_in[2];
    const float* W1      = (const float*)d_in[3];
    const float* b1      = (const float*)d_in[4];
    const float* W2      = (const float*)d_in[5];
    const float* b2      = (const float*)d_in[6];
    float*       out     = (float*)d_out;

    int B = in_sizes[0] / DDIM;           // 16384
    int gy = (B + 127) / 128 + PNUM;      // <= 136
    if (gy > MAXT) gy = MAXT;

    cudaFuncSetAttribute(k_mma<1>, cudaFuncAttributeMaxDynamicSharedMemorySize, SMEM_TOTAL);
    cudaFuncSetAttribute(k_mma<2>, cudaFuncAttributeMaxDynamicSharedMemorySize, SMEM_TOTAL);

    k_init<<<1, 32>>>((const int*)pidx, B);
    k_count<<<(B + 255) / 256, 256>>>(pidx, B);
    k_plan<<<1, 1>>>();
    k_scatter<<<(B + 255) / 256, 256>>>(pidx, B);

    k_mma<1><<<dim3(HDIM / 128, gy), 256, SMEM_TOTAL>>>(latents, actions, W1, b1, nullptr);
    k_mma<2><<<dim3(DDIM / 128, gy), 256, SMEM_TOTAL>>>(latents, actions, W2, b2, out);
}